// round 13
// baseline (speedup 1.0000x reference)
#include <cuda_runtime.h>
#include <cstdint>

#define N_   8
#define C_   64
#define H_   256
#define W_   256
#define G_   8
#define CPG_ 8               // channels per group
#define ROWS 8               // rows per block strip
#define TR   (ROWS+2)        // tile rows incl. halo
#define CHUNKS (H_/ROWS)     // 32
#define EPS_ 1e-5f
#define NT   128             // 64 col-groups x 2 row-groups
#define W4_  (W_/4)          // 64
#define TQ   (TR*W4_)        // 640 staging quads (= 5*NT exactly)
#define WP   264             // padded row width: col3 = L-halo, cols4..259 data, col260 = R-halo
#define BUFF (TR*WP)         // floats per tile buffer
#define HWQ  (H_*W_/4)

typedef unsigned long long u64;

// Static scratch (no runtime allocation)
__device__ float g_part[N_*G_*CHUNKS*2];
__device__ float g_esum[(size_t)N_*G_*H_*W_];      // per-(n,g) sum of exp
__device__ int   g_cnt[N_*CHUNKS];                 // per-cell arrival counters (zero-init, self-resetting)

// ---- f32x2 packed helpers (sm_100+) ----
__device__ __forceinline__ u64 pack2(float lo, float hi) {
    u64 r; asm("mov.b64 %0,{%1,%2};" : "=l"(r) : "f"(lo), "f"(hi)); return r;
}
__device__ __forceinline__ void unpack2(u64 v, float& lo, float& hi) {
    asm("mov.b64 {%0,%1},%2;" : "=f"(lo), "=f"(hi) : "l"(v));
}
__device__ __forceinline__ u64 fma2(u64 a, u64 b, u64 c) {
    u64 d; asm("fma.rn.f32x2 %0,%1,%2,%3;" : "=l"(d) : "l"(a), "l"(b), "l"(c)); return d;
}
__device__ __forceinline__ u64 add2(u64 a, u64 b) {
    u64 d; asm("add.rn.f32x2 %0,%1,%2;" : "=l"(d) : "l"(a), "l"(b)); return d;
}
__device__ __forceinline__ u64 mul2(u64 a, u64 b) {
    u64 d; asm("mul.rn.f32x2 %0,%1,%2;" : "=l"(d) : "l"(a), "l"(b)); return d;
}
__device__ __forceinline__ float tanh_fast(float x) {
    float y; asm("tanh.approx.f32 %0,%1;" : "=f"(y) : "f"(x)); return y;
}
__device__ __forceinline__ float ex2_fast(float x) {
    float y; asm("ex2.approx.f32 %0,%1;" : "=f"(y) : "f"(x)); return y;
}

#define CP_COMMIT() asm volatile("cp.async.commit_group;")
#define CP_WAIT1()  asm volatile("cp.async.wait_group 1;")

// Stage one (TR x W_) channel tile gmem -> padded smem rows via cp.async.cg.
__device__ __forceinline__ void cpa_tile(unsigned sbase, const float4* __restrict__ xc4,
                                         int h0, int tid) {
    #pragma unroll
    for (int i = 0; i < 5; ++i) {
        const int idx = tid + i*NT;                 // 5*128 = 640 = TQ exactly
        const int r = idx >> 6, q = idx & (W4_-1);
        const int h = h0 - 1 + r;
        const bool v = (h >= 0) && (h < H_);
        const float4* src = xc4 + (v ? (h*W4_ + q) : q);
        const int sz = v ? 16 : 0;
        const unsigned dst = sbase + (unsigned)(r*WP + 4 + 4*q)*4u;
        asm volatile("cp.async.cg.shared.global [%0], [%1], 16, %2;"
                     :: "r"(dst), "l"(src), "r"(sz));
    }
}

// 5 shifted operand pairs for one tile row, covering 4 pixels (2 f32x2 pairs)
struct RowP { u64 P0, P1, P2, P3, P4; };

__device__ __forceinline__ RowP load_row(const float* rb) {
    RowP p;
    const float  L = rb[-1];
    const float4 M = *(const float4*)rb;            // LDS.128, 16B aligned
    const float  R = rb[4];
    p.P0 = pack2(L,   M.x); p.P1 = pack2(M.x, M.y); p.P2 = pack2(M.y, M.z);
    p.P3 = pack2(M.z, M.w); p.P4 = pack2(M.w, R);
    return p;
}

#define ROW_ACC(r, b, oA, oB)                                             \
    oA = fma2((r).P0, wkp[b],   oA);                                      \
    oA = fma2((r).P1, wkp[b+1], oA);                                      \
    oA = fma2((r).P2, wkp[b+2], oA);                                      \
    oB = fma2((r).P2, wkp[b],   oB);                                      \
    oB = fma2((r).P3, wkp[b+1], oB);                                      \
    oB = fma2((r).P4, wkp[b+2], oB);

// row-sweep 3x3 conv; 1 RowP live at a time. SINK(o, cA, cB) on completion.
#define CONV_SWEEP(tb, wkp, SINK)                                         \
    {                                                                     \
        u64 oA[4] = {0,0,0,0}, oB[4] = {0,0,0,0};                         \
        _Pragma("unroll")                                                 \
        for (int tr = 0; tr < 6; ++tr) {                                  \
            RowP r = load_row((tb) + (4*ty + tr)*WP);                     \
            _Pragma("unroll")                                             \
            for (int o = 0; o < 4; ++o) {                                 \
                if (o >= tr - 2 && o <= tr) {                             \
                    ROW_ACC(r, 3*(tr - o), oA[o], oB[o]);                 \
                }                                                         \
            }                                                             \
            if (tr >= 2) { const int o = tr - 2; SINK(o, oA[o], oB[o]); } \
        }                                                                 \
    }

#define ZERO_HALOS(bufbase)                                               \
    if (tid < 3*TR*2) {                                                   \
        const int b = tid / (TR*2), rest = tid % (TR*2);                  \
        const int row = rest >> 1, col = (rest & 1) ? 260 : 3;            \
        (bufbase)[b*BUFF + row*WP + col] = 0.f;                           \
    }

#define LOAD_WEIGHTS()                                                    \
    if (tid < 9*CPG_) {                                                   \
        const int j = tid / CPG_, cc = tid % CPG_;                        \
        const float w = wgt[j*C_ + g*CPG_ + cc];                          \
        wsm2[j][cc] = make_float2(w, w);                                  \
    }

// ---------------- Pass 1: depthwise conv + per-(n,g,chunk) sum / sumsq ----------------
__global__ __launch_bounds__(NT, 8) void k_pass1(const float* __restrict__ x,
                                                 const float* __restrict__ wgt) {
    __shared__ __align__(16) float buf[3*BUFF];
    __shared__ float2 wsm2[9][CPG_];
    __shared__ float  red[4], red2[4];

    const int bid   = blockIdx.x;
    const int chunk = bid % CHUNKS;
    const int g     = (bid / CHUNKS) % G_;
    const int n     = bid / (CHUNKS * G_);
    const int h0    = chunk * ROWS;
    const int tid   = threadIdx.x;
    const int tx    = tid & 63;
    const int ty    = tid >> 6;
    const int lane  = tid & 31, wid = tid >> 5;

    ZERO_HALOS(buf);
    LOAD_WEIGHTS();

    const unsigned sb0 = (unsigned)__cvta_generic_to_shared(&buf[0]);
    const float4* x4 = (const float4*)x;
    const size_t plane0 = (size_t)(n*C_ + g*CPG_) * HWQ;

    cpa_tile(sb0,                    x4 + plane0,       h0, tid); CP_COMMIT();
    cpa_tile(sb0 + (unsigned)BUFF*4, x4 + plane0 + HWQ, h0, tid); CP_COMMIT();

    u64 gsP = 0, gs2P = 0;
    int bsel = 0;
    for (int cc = 0; cc < CPG_; ++cc) {
        CP_WAIT1();
        __syncthreads();
        if (cc + 2 < CPG_) {
            const int nb = (bsel + 2 >= 3) ? bsel - 1 : bsel + 2;
            cpa_tile(sb0 + (unsigned)(nb*BUFF)*4, x4 + plane0 + (size_t)(cc+2)*HWQ, h0, tid);
        }
        CP_COMMIT();

        u64 wkp[9];
        #pragma unroll
        for (int j = 0; j < 9; ++j) wkp[j] = *(const u64*)&wsm2[j][cc];

        const float* tb = buf + bsel*BUFF + 4 + 4*tx;
        #define SINK1(o, cA, cB)                                          \
            gsP  = add2(gsP, add2(cA, cB));                               \
            gs2P = fma2(cA, cA, gs2P);                                    \
            gs2P = fma2(cB, cB, gs2P);
        CONV_SWEEP(tb, wkp, SINK1);
        #undef SINK1
        bsel = (bsel + 1 == 3) ? 0 : bsel + 1;
    }

    float a, b, gs, gs2;
    unpack2(gsP,  a, b); gs  = a + b;
    unpack2(gs2P, a, b); gs2 = a + b;
    #pragma unroll
    for (int off = 16; off; off >>= 1) {
        gs  += __shfl_down_sync(0xffffffffu, gs,  off);
        gs2 += __shfl_down_sync(0xffffffffu, gs2, off);
    }
    if (lane == 0) { red[wid] = gs; red2[wid] = gs2; }
    __syncthreads();
    if (tid == 0) {
        float s  = red[0] + red[1] + red[2] + red[3];
        float s2 = red2[0] + red2[1] + red2[2] + red2[3];
        const int idx = ((n*G_ + g)*CHUNKS + chunk)*2;
        g_part[idx]   = s;
        g_part[idx+1] = s2;
    }
}

// ---------------- Pass 2 (fused): conv + norm/act/residual + group exp-sum;
// the last group-block per (n,chunk) cell also does LSE + 64-channel broadcast write.
__global__ __launch_bounds__(NT, 8) void k_pass2(const float* __restrict__ x,
                                                 const float* __restrict__ wgt,
                                                 float* __restrict__ out) {
    __shared__ __align__(16) float buf[3*BUFF];
    __shared__ float2 wsm2[9][CPG_];
    __shared__ float  s_stats[2];
    __shared__ int    s_ticket;

    // bid: cell-major so a cell's 8 group-blocks are consecutive; reversed for L2 reuse
    const int bid   = (gridDim.x - 1) - blockIdx.x;
    const int g     = bid % G_;
    const int cell  = bid / G_;                     // n*CHUNKS + chunk
    const int chunk = cell % CHUNKS;
    const int n     = cell / CHUNKS;
    const int h0    = chunk * ROWS;
    const int tid   = threadIdx.x;
    const int tx    = tid & 63;
    const int ty    = tid >> 6;

    ZERO_HALOS(buf);
    LOAD_WEIGHTS();
    // fold stats reduce: 32 chunk-partials for this (n,g), warp 3
    if (tid >= 96) {
        const int l = tid - 96;
        const int sg = (n*G_ + g)*CHUNKS;
        float s  = g_part[(sg + l)*2];
        float s2 = g_part[(sg + l)*2 + 1];
        #pragma unroll
        for (int off = 16; off; off >>= 1) {
            s  += __shfl_down_sync(0xffffffffu, s,  off);
            s2 += __shfl_down_sync(0xffffffffu, s2, off);
        }
        if (l == 0) {
            const float inv = 1.0f / (float)(CPG_*H_*W_);
            const float m = s * inv;
            const float v = s2 * inv - m*m;
            s_stats[0] = m;
            s_stats[1] = rsqrtf(v + EPS_);
        }
    }

    const unsigned sb0 = (unsigned)__cvta_generic_to_shared(&buf[0]);
    const float4* x4 = (const float4*)x;
    const size_t plane0 = (size_t)(n*C_ + g*CPG_) * HWQ;

    cpa_tile(sb0,                    x4 + plane0,       h0, tid); CP_COMMIT();
    cpa_tile(sb0 + (unsigned)BUFF*4, x4 + plane0 + HWQ, h0, tid); CP_COMMIT();

    u64 acc[8];                                     // 4 rows x {A,B}
    #pragma unroll
    for (int i = 0; i < 8; ++i) acc[i] = 0;

    const u64 threeP = pack2(3.0f, 3.0f);
    const u64 sixthP = pack2(1.0f/6.0f, 1.0f/6.0f);
    const u64 log2eP = pack2(1.4426950408889634f, 1.4426950408889634f);

    int bsel = 0;
    for (int cc = 0; cc < CPG_; ++cc) {
        CP_WAIT1();
        __syncthreads();                            // also publishes s_stats
        const float mean = s_stats[0];
        const float rstd = s_stats[1];
        const u64 rstdP = pack2(rstd, rstd);
        const u64 nmrP  = pack2(-mean*rstd, -mean*rstd);
        if (cc + 2 < CPG_) {
            const int nb = (bsel + 2 >= 3) ? bsel - 1 : bsel + 2;
            cpa_tile(sb0 + (unsigned)(nb*BUFF)*4, x4 + plane0 + (size_t)(cc+2)*HWQ, h0, tid);
        }
        CP_COMMIT();

        u64 wkp[9];
        #pragma unroll
        for (int j = 0; j < 9; ++j) wkp[j] = *(const u64*)&wsm2[j][cc];

        const float* tb = buf + bsel*BUFF + 4 + 4*tx;
        #define SINK2(o, cA, cB)                                          \
            {                                                             \
                u64 cv2[2] = { cA, cB };                                  \
                _Pragma("unroll")                                         \
                for (int h = 0; h < 2; ++h) {                             \
                    const u64 vP = fma2(cv2[h], rstdP, nmrP);             \
                    float v0, v1; unpack2(vP, v0, v1);                    \
                    const u64 tP = pack2(tanh_fast(v0), tanh_fast(v1));   \
                    const u64 xrP = fma2(mul2(tP, sixthP), add2(tP, threeP), cv2[h]); \
                    const u64 aP  = mul2(xrP, log2eP);                    \
                    float a0, a1; unpack2(aP, a0, a1);                    \
                    const u64 eP = pack2(ex2_fast(a0), ex2_fast(a1));     \
                    acc[(o)*2+h] = add2(acc[(o)*2+h], eP);                \
                }                                                         \
            }
        CONV_SWEEP(tb, wkp, SINK2);
        #undef SINK2
        bsel = (bsel + 1 == 3) ? 0 : bsel + 1;
    }

    // write this group's esum strip
    float* es = g_esum + ((size_t)(n*G_ + g)*H_ + h0 + 4*ty)*W_ + 4*tx;
    #pragma unroll
    for (int rr = 0; rr < 4; ++rr) {
        float4 o;
        unpack2(acc[rr*2+0], o.x, o.y);
        unpack2(acc[rr*2+1], o.z, o.w);
        *(float4*)(es + rr*W_) = o;
    }

    // ---- last-block-per-cell: LSE + broadcast write ----
    __threadfence();
    if (tid == 0) s_ticket = atomicAdd(&g_cnt[cell], 1);
    __syncthreads();
    if (s_ticket != G_ - 1) return;

    if (tid == 0) g_cnt[cell] = 0;                  // restore zero-invariant for next launch

    // stage log(sum over 8 groups) for this 8x256 strip into smem (buf now free)
    float4* lse4 = (float4*)buf;                    // 512 quads = 8 KB
    const float4* e4 = (const float4*)g_esum;
    #pragma unroll
    for (int i = tid; i < ROWS*W4_; i += NT) {      // 512 quads, 4 per thread
        const int r = i >> 6, q = i & (W4_-1);
        const size_t base = ((size_t)(n*G_)*H_ + h0 + r)*W4_ + q;
        float4 s = __ldg(&e4[base]);
        #pragma unroll
        for (int gg = 1; gg < G_; ++gg) {
            const float4 v = __ldg(&e4[base + (size_t)gg*H_*W4_]);
            s.x += v.x; s.y += v.y; s.z += v.z; s.w += v.w;
        }
        float4 L;
        L.x = __logf(s.x); L.y = __logf(s.y); L.z = __logf(s.z); L.w = __logf(s.w);
        lse4[i] = L;
    }
    __syncthreads();

    // broadcast to all 64 channels with streaming stores
    float4* o4 = (float4*)out;
    for (int i = tid; i < C_*ROWS*W4_; i += NT) {   // 32768 quads
        const int q  = i & (ROWS*W4_ - 1);          // quad within strip
        const int c  = i >> 9;
        const int r  = q >> 6, qq = q & (W4_-1);
        const float4 v = lse4[q];
        const size_t off = ((size_t)(n*C_ + c)*H_ + h0 + r)*W4_ + qq;
        __stcs(&o4[off], v);
    }
}

extern "C" void kernel_launch(void* const* d_in, const int* in_sizes, int n_in,
                              void* d_out, int out_size) {
    const float* x   = (const float*)d_in[0];       // [8,64,256,256]
    const float* wgt = (const float*)d_in[1];       // [3,3,64]
    float* out = (float*)d_out;

    k_pass1<<<N_*G_*CHUNKS, NT>>>(x, wgt);
    k_pass2<<<N_*G_*CHUNKS, NT>>>(x, wgt, out);
}

// round 14
// speedup vs baseline: 1.1324x; 1.1324x over previous
#include <cuda_runtime.h>
#include <cstdint>

#define N_   8
#define C_   64
#define H_   256
#define W_   256
#define G_   8
#define CPG_ 8               // channels per group
#define ROWS 8               // rows per block strip
#define TR   (ROWS+2)        // tile rows incl. halo
#define CHUNKS (H_/ROWS)     // 32
#define EPS_ 1e-5f
#define NT   256             // one column per thread
#define W4_  (W_/4)          // 64
#define TQ   (TR*W4_)        // 640 staging quads
#define WP   264             // padded row width: col3 = L-halo, cols4..259 data, col260 = R-halo
#define BUFF (TR*WP)         // floats per tile buffer
#define HWQ  (H_*W_/4)
#define CSPLIT 4
#define CHPB (C_/CSPLIT)     // 16 channels per pass2b block

typedef unsigned long long u64;

// Static scratch (no runtime allocation)
__device__ float g_part[N_*G_*CHUNKS*2];
__device__ float g_esum[(size_t)N_*G_*H_*W_];      // per-(n,g) sum of exp

// ---- f32x2 packed helpers (sm_100+) ----
__device__ __forceinline__ u64 pack2(float lo, float hi) {
    u64 r; asm("mov.b64 %0,{%1,%2};" : "=l"(r) : "f"(lo), "f"(hi)); return r;
}
__device__ __forceinline__ void unpack2(u64 v, float& lo, float& hi) {
    asm("mov.b64 {%0,%1},%2;" : "=f"(lo), "=f"(hi) : "l"(v));
}
__device__ __forceinline__ u64 fma2(u64 a, u64 b, u64 c) {
    u64 d; asm("fma.rn.f32x2 %0,%1,%2,%3;" : "=l"(d) : "l"(a), "l"(b), "l"(c)); return d;
}
__device__ __forceinline__ u64 add2(u64 a, u64 b) {
    u64 d; asm("add.rn.f32x2 %0,%1,%2;" : "=l"(d) : "l"(a), "l"(b)); return d;
}
__device__ __forceinline__ u64 mul2(u64 a, u64 b) {
    u64 d; asm("mul.rn.f32x2 %0,%1,%2;" : "=l"(d) : "l"(a), "l"(b)); return d;
}
__device__ __forceinline__ float tanh_fast(float x) {
    float y; asm("tanh.approx.f32 %0,%1;" : "=f"(y) : "f"(x)); return y;
}
__device__ __forceinline__ float ex2_fast(float x) {
    float y; asm("ex2.approx.f32 %0,%1;" : "=f"(y) : "f"(x)); return y;
}

#define CP_COMMIT() asm volatile("cp.async.commit_group;")
#define CP_WAIT1()  asm volatile("cp.async.wait_group 1;")

// Stage one (TR x W_) channel tile gmem -> padded smem rows via cp.async.cg.
__device__ __forceinline__ void cpa_tile(unsigned sbase, const float4* __restrict__ xc4,
                                         int h0, int tid) {
    #pragma unroll
    for (int i = 0; i < 3; ++i) {
        const int idx = tid + i*NT;
        if (idx < TQ) {
            const int r = idx >> 6, q = idx & (W4_-1);
            const int h = h0 - 1 + r;
            const bool v = (h >= 0) && (h < H_);
            const float4* src = xc4 + (v ? (h*W4_ + q) : q);
            const int sz = v ? 16 : 0;
            const unsigned dst = sbase + (unsigned)(r*WP + 4 + 4*q)*4u;
            asm volatile("cp.async.cg.shared.global [%0], [%1], 16, %2;"
                         :: "r"(dst), "l"(src), "r"(sz));
        }
    }
}

// Vertical-pair 3x3 conv sweep: thread owns column tid; outputs = 4 f32x2 pairs
// (rows 2p, 2p+1). All LDS scalar, 4B lane stride -> conflict-free.
// SINK(p, O) fires when output pair p completes.
#define CONV_SWEEP_V(tb, wkp, SINK)                                       \
    {                                                                     \
        u64 O_[4] = {0,0,0,0};                                            \
        float lA = (tb)[0], mA = (tb)[1], rA = (tb)[2];   /* tile row 0 */\
        _Pragma("unroll")                                                 \
        for (int r = 1; r <= 9; ++r) {                                    \
            const float* rw = (tb) + r*WP;                                \
            const float lB = rw[0], mB = rw[1], rB = rw[2];               \
            const u64 PL = pack2(lA, lB);                                 \
            const u64 PM = pack2(mA, mB);                                 \
            const u64 PR = pack2(rA, rB);                                 \
            const int q = r - 1;          /* packed input pair (q,q+1) */ \
            if (q & 1) {                  /* kernel row 1 -> p=(q-1)/2 */ \
                const int p = (q-1) >> 1;                                 \
                O_[p] = fma2(PL, wkp[3], O_[p]);                          \
                O_[p] = fma2(PM, wkp[4], O_[p]);                          \
                O_[p] = fma2(PR, wkp[5], O_[p]);                          \
            } else {                                                      \
                if (q <= 6) {             /* kernel row 0 -> p=q/2   */   \
                    const int p = q >> 1;                                 \
                    O_[p] = fma2(PL, wkp[0], O_[p]);                      \
                    O_[p] = fma2(PM, wkp[1], O_[p]);                      \
                    O_[p] = fma2(PR, wkp[2], O_[p]);                      \
                }                                                         \
                if (q >= 2) {             /* kernel row 2 -> p=(q-2)/2 */ \
                    const int p = (q-2) >> 1;                             \
                    O_[p] = fma2(PL, wkp[6], O_[p]);                      \
                    O_[p] = fma2(PM, wkp[7], O_[p]);                      \
                    O_[p] = fma2(PR, wkp[8], O_[p]);                      \
                    SINK(p, O_[p]);       /* pair p now complete */       \
                }                                                         \
            }                                                             \
            lA = lB; mA = mB; rA = rB;                                    \
        }                                                                 \
    }

// zero halo columns (cols 3 and 260) of all TR rows in all 3 buffers
#define ZERO_HALOS(bufbase)                                               \
    if (tid < 3*TR*2) {                                                   \
        const int b = tid / (TR*2), rest = tid % (TR*2);                  \
        const int row = rest >> 1, col = (rest & 1) ? 260 : 3;            \
        (bufbase)[b*BUFF + row*WP + col] = 0.f;                           \
    }

#define LOAD_WEIGHTS()                                                    \
    if (tid >= 64 && tid < 64 + 9*CPG_) {                                 \
        const int t = tid - 64;                                           \
        const int j = t / CPG_, cc = t % CPG_;                            \
        const float w = wgt[j*C_ + g*CPG_ + cc];                          \
        wsm2[j][cc] = make_float2(w, w);                                  \
    }

// ---------------- Pass 1: depthwise conv + per-(n,g,chunk) sum / sumsq ----------------
__global__ __launch_bounds__(NT, 5) void k_pass1(const float* __restrict__ x,
                                                 const float* __restrict__ wgt) {
    __shared__ __align__(16) float buf[3*BUFF];
    __shared__ float2 wsm2[9][CPG_];
    __shared__ float  red[8], red2[8];

    const int bid   = blockIdx.x;
    const int chunk = bid % CHUNKS;
    const int g     = (bid / CHUNKS) % G_;
    const int n     = bid / (CHUNKS * G_);
    const int h0    = chunk * ROWS;
    const int tid   = threadIdx.x;                  // = column
    const int lane  = tid & 31, wid = tid >> 5;

    ZERO_HALOS(buf);
    LOAD_WEIGHTS();

    const unsigned sb0 = (unsigned)__cvta_generic_to_shared(&buf[0]);
    const float4* x4 = (const float4*)x;
    const size_t plane0 = (size_t)(n*C_ + g*CPG_) * HWQ;

    cpa_tile(sb0,                    x4 + plane0,       h0, tid); CP_COMMIT();
    cpa_tile(sb0 + (unsigned)BUFF*4, x4 + plane0 + HWQ, h0, tid); CP_COMMIT();

    u64 gsP = 0, gs2P = 0;
    int bsel = 0;
    for (int cc = 0; cc < CPG_; ++cc) {
        CP_WAIT1();
        __syncthreads();
        if (cc + 2 < CPG_) {
            const int nb = (bsel + 2 >= 3) ? bsel - 1 : bsel + 2;
            cpa_tile(sb0 + (unsigned)(nb*BUFF)*4, x4 + plane0 + (size_t)(cc+2)*HWQ, h0, tid);
        }
        CP_COMMIT();

        u64 wkp[9];
        #pragma unroll
        for (int j = 0; j < 9; ++j) wkp[j] = *(const u64*)&wsm2[j][cc];

        const float* tb = buf + bsel*BUFF + 3 + tid;   // L at [0], M at [1], R at [2]
        #define SINK1(p, O)                                               \
            gsP  = add2(gsP, O);                                          \
            gs2P = fma2(O, O, gs2P);
        CONV_SWEEP_V(tb, wkp, SINK1);
        #undef SINK1
        bsel = (bsel + 1 == 3) ? 0 : bsel + 1;
    }

    float a, b, gs, gs2;
    unpack2(gsP,  a, b); gs  = a + b;
    unpack2(gs2P, a, b); gs2 = a + b;
    #pragma unroll
    for (int off = 16; off; off >>= 1) {
        gs  += __shfl_down_sync(0xffffffffu, gs,  off);
        gs2 += __shfl_down_sync(0xffffffffu, gs2, off);
    }
    if (lane == 0) { red[wid] = gs; red2[wid] = gs2; }
    __syncthreads();
    if (wid == 0) {
        float s  = (lane < 8) ? red[lane]  : 0.f;
        float s2 = (lane < 8) ? red2[lane] : 0.f;
        #pragma unroll
        for (int off = 4; off; off >>= 1) {
            s  += __shfl_down_sync(0xffffffffu, s,  off);
            s2 += __shfl_down_sync(0xffffffffu, s2, off);
        }
        if (lane == 0) {
            const int idx = ((n*G_ + g)*CHUNKS + chunk)*2;
            g_part[idx]   = s;
            g_part[idx+1] = s2;
        }
    }
}

// ---------------- Pass 2a: conv recompute + norm/act/residual + group exp-sum ----------------
__global__ __launch_bounds__(NT, 5) void k_pass2a(const float* __restrict__ x,
                                                  const float* __restrict__ wgt) {
    __shared__ __align__(16) float buf[3*BUFF];
    __shared__ float2 wsm2[9][CPG_];
    __shared__ float  s_stats[2];

    const int bid   = (gridDim.x - 1) - blockIdx.x;   // reversed for L2 reuse
    const int chunk = bid % CHUNKS;
    const int g     = (bid / CHUNKS) % G_;
    const int n     = bid / (CHUNKS * G_);
    const int h0    = chunk * ROWS;
    const int tid   = threadIdx.x;
    const int lane  = tid & 31;

    ZERO_HALOS(buf);
    LOAD_WEIGHTS();
    // fold stats reduce: 32 chunk-partials for this (n,g), warp 7
    if (tid >= 224) {
        const int l = tid - 224;
        const int sg = (n*G_ + g)*CHUNKS;
        float s  = g_part[(sg + l)*2];
        float s2 = g_part[(sg + l)*2 + 1];
        #pragma unroll
        for (int off = 16; off; off >>= 1) {
            s  += __shfl_down_sync(0xffffffffu, s,  off);
            s2 += __shfl_down_sync(0xffffffffu, s2, off);
        }
        if (l == 0) {
            const float inv = 1.0f / (float)(CPG_*H_*W_);
            const float m = s * inv;
            const float v = s2 * inv - m*m;
            s_stats[0] = m;
            s_stats[1] = rsqrtf(v + EPS_);
        }
    }

    const unsigned sb0 = (unsigned)__cvta_generic_to_shared(&buf[0]);
    const float4* x4 = (const float4*)x;
    const size_t plane0 = (size_t)(n*C_ + g*CPG_) * HWQ;

    cpa_tile(sb0,                    x4 + plane0,       h0, tid); CP_COMMIT();
    cpa_tile(sb0 + (unsigned)BUFF*4, x4 + plane0 + HWQ, h0, tid); CP_COMMIT();

    u64 acc[4];                                     // 4 vertical pairs (rows 2p,2p+1)
    #pragma unroll
    for (int i = 0; i < 4; ++i) acc[i] = 0;

    const u64 threeP = pack2(3.0f, 3.0f);
    const u64 sixthP = pack2(1.0f/6.0f, 1.0f/6.0f);
    const u64 log2eP = pack2(1.4426950408889634f, 1.4426950408889634f);

    int bsel = 0;
    for (int cc = 0; cc < CPG_; ++cc) {
        CP_WAIT1();
        __syncthreads();                            // also publishes s_stats
        const float mean = s_stats[0];
        const float rstd = s_stats[1];
        const u64 rstdP = pack2(rstd, rstd);
        const u64 nmrP  = pack2(-mean*rstd, -mean*rstd);
        if (cc + 2 < CPG_) {
            const int nb = (bsel + 2 >= 3) ? bsel - 1 : bsel + 2;
            cpa_tile(sb0 + (unsigned)(nb*BUFF)*4, x4 + plane0 + (size_t)(cc+2)*HWQ, h0, tid);
        }
        CP_COMMIT();

        u64 wkp[9];
        #pragma unroll
        for (int j = 0; j < 9; ++j) wkp[j] = *(const u64*)&wsm2[j][cc];

        const float* tb = buf + bsel*BUFF + 3 + tid;
        #define SINK2(p, O)                                               \
            {                                                             \
                const u64 vP = fma2(O, rstdP, nmrP);                      \
                float v0, v1; unpack2(vP, v0, v1);                        \
                const u64 tP = pack2(tanh_fast(v0), tanh_fast(v1));       \
                const u64 xrP = fma2(mul2(tP, sixthP), add2(tP, threeP), O); \
                const u64 aP  = mul2(xrP, log2eP);                        \
                float a0, a1; unpack2(aP, a0, a1);                        \
                const u64 eP = pack2(ex2_fast(a0), ex2_fast(a1));         \
                acc[p] = add2(acc[p], eP);                                \
            }
        CONV_SWEEP_V(tb, wkp, SINK2);
        #undef SINK2
        bsel = (bsel + 1 == 3) ? 0 : bsel + 1;
    }

    // store 8 rows for this column (coalesced across threads)
    float* es = g_esum + ((size_t)(n*G_ + g)*H_ + h0)*W_ + tid;
    #pragma unroll
    for (int p = 0; p < 4; ++p) {
        float lo, hi;
        unpack2(acc[p], lo, hi);
        es[(2*p  )*W_] = lo;
        es[(2*p+1)*W_] = hi;
    }
}

// ---------------- Pass 2b: combine groups, log, broadcast 16 channels/block ----------------
__global__ __launch_bounds__(256) void k_pass2b(float* __restrict__ out) {
    const int p   = blockIdx.x * 256 + threadIdx.x;
    const int n   = p >> 14;
    const int pix = p & (HWQ - 1);
    const int c0  = blockIdx.y * CHPB;

    const float4* e4 = (const float4*)g_esum;
    const size_t ebase = (size_t)n*G_*HWQ + pix;
    float4 s = __ldg(&e4[ebase]);
    #pragma unroll
    for (int g = 1; g < G_; ++g) {
        const float4 v = __ldg(&e4[ebase + (size_t)g*HWQ]);
        s.x += v.x; s.y += v.y; s.z += v.z; s.w += v.w;
    }
    float4 L;
    L.x = __logf(s.x); L.y = __logf(s.y); L.z = __logf(s.z); L.w = __logf(s.w);

    float4* o4 = (float4*)out;
    const size_t obase = (size_t)n*C_*HWQ + (size_t)c0*HWQ + pix;
    #pragma unroll
    for (int c = 0; c < CHPB; ++c) __stcs(&o4[obase + (size_t)c*HWQ], L);
}

extern "C" void kernel_launch(void* const* d_in, const int* in_sizes, int n_in,
                              void* d_out, int out_size) {
    const float* x   = (const float*)d_in[0];       // [8,64,256,256]
    const float* wgt = (const float*)d_in[1];       // [3,3,64]
    float* out = (float*)d_out;

    k_pass1 <<<N_*G_*CHUNKS, NT>>>(x, wgt);
    k_pass2a<<<N_*G_*CHUNKS, NT>>>(x, wgt);
    k_pass2b<<<dim3((N_*HWQ)/256, CSPLIT), 256>>>(out);
}

// round 15
// speedup vs baseline: 1.5617x; 1.3792x over previous
#include <cuda_runtime.h>
#include <cuda_fp16.h>
#include <cstdint>

#define N_   8
#define C_   64
#define H_   256
#define W_   256
#define G_   8
#define CPG_ 8               // channels per group
#define ROWS 8               // rows per block strip
#define TR   (ROWS+2)        // tile rows incl. halo
#define CHUNKS (H_/ROWS)     // 32
#define EPS_ 1e-5f
#define NT   128             // 64 col-groups x 2 row-groups
#define W4_  (W_/4)          // 64
#define TQ   (TR*W4_)        // 640 staging quads (= 5*NT exactly)
#define WP   264             // padded row width: col3 = L-halo, cols4..259 data, col260 = R-halo
#define BUFF (TR*WP)         // floats per tile buffer
#define HW_  (H_*W_)
#define HWQ  (HW_/4)
#define CSPLIT 4
#define CHPB (C_/CSPLIT)     // 16 channels per pass2b block
#define PXT  8               // pixels per thread in pass2a
#define SEGS (HW_/(256*PXT)) // 32 segments per (n,g) plane

typedef unsigned long long u64;

// Static scratch (no runtime allocation)
__device__ float  g_part[N_*G_*CHUNKS*2];
__device__ __half g_conv[(size_t)N_*C_*HW_];        // conv output, fp16 (67 MB)
__device__ float  g_esum[(size_t)N_*G_*HW_];        // per-(n,g) sum of exp (16.8 MB)

// ---- f32x2 packed helpers (sm_100+) ----
__device__ __forceinline__ u64 pack2(float lo, float hi) {
    u64 r; asm("mov.b64 %0,{%1,%2};" : "=l"(r) : "f"(lo), "f"(hi)); return r;
}
__device__ __forceinline__ void unpack2(u64 v, float& lo, float& hi) {
    asm("mov.b64 {%0,%1},%2;" : "=f"(lo), "=f"(hi) : "l"(v));
}
__device__ __forceinline__ u64 fma2(u64 a, u64 b, u64 c) {
    u64 d; asm("fma.rn.f32x2 %0,%1,%2,%3;" : "=l"(d) : "l"(a), "l"(b), "l"(c)); return d;
}
__device__ __forceinline__ u64 add2(u64 a, u64 b) {
    u64 d; asm("add.rn.f32x2 %0,%1,%2;" : "=l"(d) : "l"(a), "l"(b)); return d;
}
__device__ __forceinline__ float tanh_fast(float x) {
    float y; asm("tanh.approx.f32 %0,%1;" : "=f"(y) : "f"(x)); return y;
}
__device__ __forceinline__ float ex2_fast(float x) {
    float y; asm("ex2.approx.f32 %0,%1;" : "=f"(y) : "f"(x)); return y;
}

#define CP_COMMIT() asm volatile("cp.async.commit_group;")
#define CP_WAIT1()  asm volatile("cp.async.wait_group 1;")

// Stage one (TR x W_) channel tile gmem -> padded smem rows via cp.async.cg.
__device__ __forceinline__ void cpa_tile(unsigned sbase, const float4* __restrict__ xc4,
                                         int h0, int tid) {
    #pragma unroll
    for (int i = 0; i < 5; ++i) {
        const int idx = tid + i*NT;                 // 5*128 = 640 = TQ exactly
        const int r = idx >> 6, q = idx & (W4_-1);
        const int h = h0 - 1 + r;
        const bool v = (h >= 0) && (h < H_);
        const float4* src = xc4 + (v ? (h*W4_ + q) : q);
        const int sz = v ? 16 : 0;
        const unsigned dst = sbase + (unsigned)(r*WP + 4 + 4*q)*4u;
        asm volatile("cp.async.cg.shared.global [%0], [%1], 16, %2;"
                     :: "r"(dst), "l"(src), "r"(sz));
    }
}

// 5 shifted operand pairs for one tile row, covering 4 pixels (2 f32x2 pairs)
struct RowP { u64 P0, P1, P2, P3, P4; };

__device__ __forceinline__ RowP load_row(const float* rb) {
    RowP p;
    const float  L = rb[-1];
    const float4 M = *(const float4*)rb;            // LDS.128, 16B aligned
    const float  R = rb[4];
    p.P0 = pack2(L,   M.x); p.P1 = pack2(M.x, M.y); p.P2 = pack2(M.y, M.z);
    p.P3 = pack2(M.z, M.w); p.P4 = pack2(M.w, R);
    return p;
}

#define ROW_ACC(r, b, oA, oB)                                             \
    oA = fma2((r).P0, wkp[b],   oA);                                      \
    oA = fma2((r).P1, wkp[b+1], oA);                                      \
    oA = fma2((r).P2, wkp[b+2], oA);                                      \
    oB = fma2((r).P2, wkp[b],   oB);                                      \
    oB = fma2((r).P3, wkp[b+1], oB);                                      \
    oB = fma2((r).P4, wkp[b+2], oB);

// row-sweep 3x3 conv; 1 RowP live at a time. SINK(o, cA, cB) on completion.
#define CONV_SWEEP(tb, wkp, SINK)                                         \
    {                                                                     \
        u64 oA[4] = {0,0,0,0}, oB[4] = {0,0,0,0};                         \
        _Pragma("unroll")                                                 \
        for (int tr = 0; tr < 6; ++tr) {                                  \
            RowP r = load_row((tb) + (4*ty + tr)*WP);                     \
            _Pragma("unroll")                                             \
            for (int o = 0; o < 4; ++o) {                                 \
                if (o >= tr - 2 && o <= tr) {                             \
                    ROW_ACC(r, 3*(tr - o), oA[o], oB[o]);                 \
                }                                                         \
            }                                                             \
            if (tr >= 2) { const int o = tr - 2; SINK(o, oA[o], oB[o]); } \
        }                                                                 \
    }

#define ZERO_HALOS(bufbase)                                               \
    if (tid < 3*TR*2) {                                                   \
        const int b = tid / (TR*2), rest = tid % (TR*2);                  \
        const int row = rest >> 1, col = (rest & 1) ? 260 : 3;            \
        (bufbase)[b*BUFF + row*WP + col] = 0.f;                           \
    }

#define LOAD_WEIGHTS()                                                    \
    if (tid < 9*CPG_) {                                                   \
        const int j = tid / CPG_, cc = tid % CPG_;                        \
        const float w = wgt[j*C_ + g*CPG_ + cc];                          \
        wsm2[j][cc] = make_float2(w, w);                                  \
    }

// ---------------- Pass 1: depthwise conv -> fp16 conv store + per-(n,g,chunk) stats ----------------
__global__ __launch_bounds__(NT, 8) void k_pass1(const float* __restrict__ x,
                                                 const float* __restrict__ wgt) {
    __shared__ __align__(16) float buf[3*BUFF];
    __shared__ float2 wsm2[9][CPG_];
    __shared__ float  red[4], red2[4];

    const int bid   = blockIdx.x;
    const int chunk = bid % CHUNKS;
    const int g     = (bid / CHUNKS) % G_;
    const int n     = bid / (CHUNKS * G_);
    const int h0    = chunk * ROWS;
    const int tid   = threadIdx.x;
    const int tx    = tid & 63;                     // cols 4tx..4tx+3
    const int ty    = tid >> 6;                     // rows 4ty..4ty+3
    const int lane  = tid & 31, wid = tid >> 5;

    ZERO_HALOS(buf);
    LOAD_WEIGHTS();

    const unsigned sb0 = (unsigned)__cvta_generic_to_shared(&buf[0]);
    const float4* x4 = (const float4*)x;
    const size_t plane0 = (size_t)(n*C_ + g*CPG_) * HWQ;

    cpa_tile(sb0,                    x4 + plane0,       h0, tid); CP_COMMIT();
    cpa_tile(sb0 + (unsigned)BUFF*4, x4 + plane0 + HWQ, h0, tid); CP_COMMIT();

    u64 gsP = 0, gs2P = 0;
    int bsel = 0;
    for (int cc = 0; cc < CPG_; ++cc) {
        CP_WAIT1();
        __syncthreads();
        if (cc + 2 < CPG_) {
            const int nb = (bsel + 2 >= 3) ? bsel - 1 : bsel + 2;
            cpa_tile(sb0 + (unsigned)(nb*BUFF)*4, x4 + plane0 + (size_t)(cc+2)*HWQ, h0, tid);
        }
        CP_COMMIT();

        u64 wkp[9];
        #pragma unroll
        for (int j = 0; j < 9; ++j) wkp[j] = *(const u64*)&wsm2[j][cc];

        // conv output pointer for this channel / thread patch (8B aligned)
        __half* cvp = g_conv + ((size_t)(n*C_ + g*CPG_ + cc)*H_ + h0 + 4*ty)*W_ + 4*tx;

        const float* tb = buf + bsel*BUFF + 4 + 4*tx;
        #define SINK1(o, cA, cB)                                          \
            gsP  = add2(gsP, add2(cA, cB));                               \
            gs2P = fma2(cA, cA, gs2P);                                    \
            gs2P = fma2(cB, cB, gs2P);                                    \
            {                                                             \
                float a0, a1, b0, b1;                                     \
                unpack2(cA, a0, a1); unpack2(cB, b0, b1);                 \
                __half2 hA = __floats2half2_rn(a0, a1);                   \
                __half2 hB = __floats2half2_rn(b0, b1);                   \
                uint2 u;                                                  \
                u.x = *(unsigned*)&hA; u.y = *(unsigned*)&hB;             \
                *(uint2*)(cvp + (o)*W_) = u;                              \
            }
        CONV_SWEEP(tb, wkp, SINK1);
        #undef SINK1
        bsel = (bsel + 1 == 3) ? 0 : bsel + 1;
    }

    float a, b, gs, gs2;
    unpack2(gsP,  a, b); gs  = a + b;
    unpack2(gs2P, a, b); gs2 = a + b;
    #pragma unroll
    for (int off = 16; off; off >>= 1) {
        gs  += __shfl_down_sync(0xffffffffu, gs,  off);
        gs2 += __shfl_down_sync(0xffffffffu, gs2, off);
    }
    if (lane == 0) { red[wid] = gs; red2[wid] = gs2; }
    __syncthreads();
    if (tid == 0) {
        float s  = red[0] + red[1] + red[2] + red[3];
        float s2 = red2[0] + red2[1] + red2[2] + red2[3];
        const int idx = ((n*G_ + g)*CHUNKS + chunk)*2;
        g_part[idx]   = s;
        g_part[idx+1] = s2;
    }
}

// ---------------- Pass 2a (streaming): read fp16 conv, epilogue, group exp-sum ----------------
__global__ __launch_bounds__(256) void k_pass2a(float* __restrict__ dummy) {
    __shared__ float s_stats[2];

    const int bid = blockIdx.x;
    const int seg = bid % SEGS;
    const int g   = (bid / SEGS) % G_;
    const int n   = bid / (SEGS * G_);
    const int tid = threadIdx.x;

    // fold stats reduce: 32 chunk-partials for this (n,g), warp 0
    if (tid < 32) {
        const int sg = (n*G_ + g)*CHUNKS;
        float s  = g_part[(sg + tid)*2];
        float s2 = g_part[(sg + tid)*2 + 1];
        #pragma unroll
        for (int off = 16; off; off >>= 1) {
            s  += __shfl_down_sync(0xffffffffu, s,  off);
            s2 += __shfl_down_sync(0xffffffffu, s2, off);
        }
        if (tid == 0) {
            const float inv = 1.0f / (float)(CPG_*H_*W_);
            const float m = s * inv;
            const float v = s2 * inv - m*m;
            s_stats[0] = m;
            s_stats[1] = rsqrtf(v + EPS_);
        }
    }
    __syncthreads();
    const float mean = s_stats[0];
    const float rstd = s_stats[1];
    const float nmr  = -mean * rstd;
    const float L2E  = 1.4426950408889634f;

    const int px = seg*(256*PXT) + tid*PXT;         // 8 consecutive pixels

    float es[PXT];
    #pragma unroll
    for (int i = 0; i < PXT; ++i) es[i] = 0.f;

    #pragma unroll
    for (int cc = 0; cc < CPG_; ++cc) {
        const uint4 u = *(const uint4*)(g_conv + (size_t)(n*C_ + g*CPG_ + cc)*HW_ + px);
        const unsigned uw[4] = { u.x, u.y, u.z, u.w };
        #pragma unroll
        for (int j = 0; j < 4; ++j) {
            const float2 f2 = __half22float2(*(const __half2*)&uw[j]);
            const float f[2] = { f2.x, f2.y };
            #pragma unroll
            for (int k = 0; k < 2; ++k) {
                const float cv = f[k];
                const float v  = fmaf(cv, rstd, nmr);
                const float t  = tanh_fast(v);
                // t in (-1,1) => clip(t+3,0,6) == t+3: xr = cv + t*(t+3)/6
                const float xr = fmaf(t * (1.0f/6.0f), t + 3.0f, cv);
                es[j*2+k] += ex2_fast(xr * L2E);
            }
        }
    }

    float4* eo = (float4*)(g_esum + (size_t)(n*G_ + g)*HW_ + px);
    eo[0] = make_float4(es[0], es[1], es[2], es[3]);
    eo[1] = make_float4(es[4], es[5], es[6], es[7]);
}

// ---------------- Pass 2b: combine groups, log, broadcast 16 channels/block ----------------
__global__ __launch_bounds__(256) void k_pass2b(float* __restrict__ out) {
    const int p   = blockIdx.x * 256 + threadIdx.x;
    const int n   = p >> 14;
    const int pix = p & (HWQ - 1);
    const int c0  = blockIdx.y * CHPB;

    const float4* e4 = (const float4*)g_esum;
    const size_t ebase = (size_t)n*G_*HWQ + pix;
    float4 s = __ldg(&e4[ebase]);
    #pragma unroll
    for (int g = 1; g < G_; ++g) {
        const float4 v = __ldg(&e4[ebase + (size_t)g*HWQ]);
        s.x += v.x; s.y += v.y; s.z += v.z; s.w += v.w;
    }
    float4 L;
    L.x = __logf(s.x); L.y = __logf(s.y); L.z = __logf(s.z); L.w = __logf(s.w);

    float4* o4 = (float4*)out;
    const size_t obase = (size_t)n*C_*HWQ + (size_t)c0*HWQ + pix;
    #pragma unroll
    for (int c = 0; c < CHPB; ++c) __stcs(&o4[obase + (size_t)c*HWQ], L);
}

extern "C" void kernel_launch(void* const* d_in, const int* in_sizes, int n_in,
                              void* d_out, int out_size) {
    const float* x   = (const float*)d_in[0];       // [8,64,256,256]
    const float* wgt = (const float*)d_in[1];       // [3,3,64]
    float* out = (float*)d_out;

    k_pass1 <<<N_*G_*CHUNKS, NT>>>(x, wgt);
    k_pass2a<<<N_*G_*SEGS, 256>>>(out);
    k_pass2b<<<dim3((N_*HWQ)/256, CSPLIT), 256>>>(out);
}

// round 16
// speedup vs baseline: 1.6405x; 1.0504x over previous
#include <cuda_runtime.h>
#include <cuda_fp16.h>
#include <cstdint>

#define N_   8
#define C_   64
#define H_   256
#define W_   256
#define G_   8
#define CPG_ 8               // channels per group
#define ROWS 8               // rows per block strip
#define TR   (ROWS+2)        // tile rows incl. halo
#define CHUNKS (H_/ROWS)     // 32
#define EPS_ 1e-5f
#define NT   128             // pass1: 64 col-groups x 2 row-groups
#define W4_  (W_/4)          // 64
#define TQ   (TR*W4_)        // 640 staging quads (= 5*NT exactly)
#define WP   264             // padded row width: col3 = L-halo, cols4..259 data, col260 = R-halo
#define BUFF (TR*WP)         // floats per tile buffer
#define HW_  (H_*W_)
#define HWQ  (HW_/4)
#define PXT2 2               // pixels per thread in fused pass2
#define SEG2 (HW_/(256*PXT2))// 128 segments per image

typedef unsigned long long u64;

// Static scratch (no runtime allocation)
__device__ float  g_part[N_*G_*CHUNKS*2];
__device__ __half g_conv[(size_t)N_*C_*HW_];        // conv output, fp16 (67 MB)

// ---- f32x2 packed helpers (sm_100+) ----
__device__ __forceinline__ u64 pack2(float lo, float hi) {
    u64 r; asm("mov.b64 %0,{%1,%2};" : "=l"(r) : "f"(lo), "f"(hi)); return r;
}
__device__ __forceinline__ void unpack2(u64 v, float& lo, float& hi) {
    asm("mov.b64 {%0,%1},%2;" : "=f"(lo), "=f"(hi) : "l"(v));
}
__device__ __forceinline__ u64 fma2(u64 a, u64 b, u64 c) {
    u64 d; asm("fma.rn.f32x2 %0,%1,%2,%3;" : "=l"(d) : "l"(a), "l"(b), "l"(c)); return d;
}
__device__ __forceinline__ u64 add2(u64 a, u64 b) {
    u64 d; asm("add.rn.f32x2 %0,%1,%2;" : "=l"(d) : "l"(a), "l"(b)); return d;
}
__device__ __forceinline__ float tanh_fast(float x) {
    float y; asm("tanh.approx.f32 %0,%1;" : "=f"(y) : "f"(x)); return y;
}
__device__ __forceinline__ float ex2_fast(float x) {
    float y; asm("ex2.approx.f32 %0,%1;" : "=f"(y) : "f"(x)); return y;
}

#define CP_COMMIT() asm volatile("cp.async.commit_group;")
#define CP_WAIT1()  asm volatile("cp.async.wait_group 1;")

// Stage one (TR x W_) channel tile gmem -> padded smem rows via cp.async.cg.
__device__ __forceinline__ void cpa_tile(unsigned sbase, const float4* __restrict__ xc4,
                                         int h0, int tid) {
    #pragma unroll
    for (int i = 0; i < 5; ++i) {
        const int idx = tid + i*NT;                 // 5*128 = 640 = TQ exactly
        const int r = idx >> 6, q = idx & (W4_-1);
        const int h = h0 - 1 + r;
        const bool v = (h >= 0) && (h < H_);
        const float4* src = xc4 + (v ? (h*W4_ + q) : q);
        const int sz = v ? 16 : 0;
        const unsigned dst = sbase + (unsigned)(r*WP + 4 + 4*q)*4u;
        asm volatile("cp.async.cg.shared.global [%0], [%1], 16, %2;"
                     :: "r"(dst), "l"(src), "r"(sz));
    }
}

// 5 shifted operand pairs for one tile row, covering 4 pixels (2 f32x2 pairs)
struct RowP { u64 P0, P1, P2, P3, P4; };

__device__ __forceinline__ RowP load_row(const float* rb) {
    RowP p;
    const float  L = rb[-1];
    const float4 M = *(const float4*)rb;            // LDS.128, 16B aligned
    const float  R = rb[4];
    p.P0 = pack2(L,   M.x); p.P1 = pack2(M.x, M.y); p.P2 = pack2(M.y, M.z);
    p.P3 = pack2(M.z, M.w); p.P4 = pack2(M.w, R);
    return p;
}

#define ROW_ACC(r, b, oA, oB)                                             \
    oA = fma2((r).P0, wkp[b],   oA);                                      \
    oA = fma2((r).P1, wkp[b+1], oA);                                      \
    oA = fma2((r).P2, wkp[b+2], oA);                                      \
    oB = fma2((r).P2, wkp[b],   oB);                                      \
    oB = fma2((r).P3, wkp[b+1], oB);                                      \
    oB = fma2((r).P4, wkp[b+2], oB);

// row-sweep 3x3 conv; 1 RowP live at a time. SINK(o, cA, cB) on completion.
#define CONV_SWEEP(tb, wkp, SINK)                                         \
    {                                                                     \
        u64 oA[4] = {0,0,0,0}, oB[4] = {0,0,0,0};                         \
        _Pragma("unroll")                                                 \
        for (int tr = 0; tr < 6; ++tr) {                                  \
            RowP r = load_row((tb) + (4*ty + tr)*WP);                     \
            _Pragma("unroll")                                             \
            for (int o = 0; o < 4; ++o) {                                 \
                if (o >= tr - 2 && o <= tr) {                             \
                    ROW_ACC(r, 3*(tr - o), oA[o], oB[o]);                 \
                }                                                         \
            }                                                             \
            if (tr >= 2) { const int o = tr - 2; SINK(o, oA[o], oB[o]); } \
        }                                                                 \
    }

#define ZERO_HALOS(bufbase)                                               \
    if (tid < 3*TR*2) {                                                   \
        const int b = tid / (TR*2), rest = tid % (TR*2);                  \
        const int row = rest >> 1, col = (rest & 1) ? 260 : 3;            \
        (bufbase)[b*BUFF + row*WP + col] = 0.f;                           \
    }

#define LOAD_WEIGHTS()                                                    \
    if (tid < 9*CPG_) {                                                   \
        const int j = tid / CPG_, cc = tid % CPG_;                        \
        const float w = wgt[j*C_ + g*CPG_ + cc];                          \
        wsm2[j][cc] = make_float2(w, w);                                  \
    }

// ---------------- Pass 1: depthwise conv -> fp16 conv store + per-(n,g,chunk) stats ----------------
__global__ __launch_bounds__(NT, 8) void k_pass1(const float* __restrict__ x,
                                                 const float* __restrict__ wgt) {
    __shared__ __align__(16) float buf[3*BUFF];
    __shared__ float2 wsm2[9][CPG_];
    __shared__ float  red[4], red2[4];

    const int bid   = blockIdx.x;
    const int chunk = bid % CHUNKS;
    const int g     = (bid / CHUNKS) % G_;
    const int n     = bid / (CHUNKS * G_);
    const int h0    = chunk * ROWS;
    const int tid   = threadIdx.x;
    const int tx    = tid & 63;                     // cols 4tx..4tx+3
    const int ty    = tid >> 6;                     // rows 4ty..4ty+3
    const int lane  = tid & 31, wid = tid >> 5;

    ZERO_HALOS(buf);
    LOAD_WEIGHTS();

    const unsigned sb0 = (unsigned)__cvta_generic_to_shared(&buf[0]);
    const float4* x4 = (const float4*)x;
    const size_t plane0 = (size_t)(n*C_ + g*CPG_) * HWQ;

    cpa_tile(sb0,                    x4 + plane0,       h0, tid); CP_COMMIT();
    cpa_tile(sb0 + (unsigned)BUFF*4, x4 + plane0 + HWQ, h0, tid); CP_COMMIT();

    u64 gsP = 0, gs2P = 0;
    int bsel = 0;
    for (int cc = 0; cc < CPG_; ++cc) {
        CP_WAIT1();
        __syncthreads();
        if (cc + 2 < CPG_) {
            const int nb = (bsel + 2 >= 3) ? bsel - 1 : bsel + 2;
            cpa_tile(sb0 + (unsigned)(nb*BUFF)*4, x4 + plane0 + (size_t)(cc+2)*HWQ, h0, tid);
        }
        CP_COMMIT();

        u64 wkp[9];
        #pragma unroll
        for (int j = 0; j < 9; ++j) wkp[j] = *(const u64*)&wsm2[j][cc];

        // conv output pointer for this channel / thread patch (8B aligned)
        __half* cvp = g_conv + ((size_t)(n*C_ + g*CPG_ + cc)*H_ + h0 + 4*ty)*W_ + 4*tx;

        const float* tb = buf + bsel*BUFF + 4 + 4*tx;
        #define SINK1(o, cA, cB)                                          \
            gsP  = add2(gsP, add2(cA, cB));                               \
            gs2P = fma2(cA, cA, gs2P);                                    \
            gs2P = fma2(cB, cB, gs2P);                                    \
            {                                                             \
                float a0, a1, b0, b1;                                     \
                unpack2(cA, a0, a1); unpack2(cB, b0, b1);                 \
                __half2 hA = __floats2half2_rn(a0, a1);                   \
                __half2 hB = __floats2half2_rn(b0, b1);                   \
                uint2 u;                                                  \
                u.x = *(unsigned*)&hA; u.y = *(unsigned*)&hB;             \
                *(uint2*)(cvp + (o)*W_) = u;                              \
            }
        CONV_SWEEP(tb, wkp, SINK1);
        #undef SINK1
        bsel = (bsel + 1 == 3) ? 0 : bsel + 1;
    }

    float a, b, gs, gs2;
    unpack2(gsP,  a, b); gs  = a + b;
    unpack2(gs2P, a, b); gs2 = a + b;
    #pragma unroll
    for (int off = 16; off; off >>= 1) {
        gs  += __shfl_down_sync(0xffffffffu, gs,  off);
        gs2 += __shfl_down_sync(0xffffffffu, gs2, off);
    }
    if (lane == 0) { red[wid] = gs; red2[wid] = gs2; }
    __syncthreads();
    if (tid == 0) {
        float s  = red[0] + red[1] + red[2] + red[3];
        float s2 = red2[0] + red2[1] + red2[2] + red2[3];
        const int idx = ((n*G_ + g)*CHUNKS + chunk)*2;
        g_part[idx]   = s;
        g_part[idx+1] = s2;
    }
}

// ---------------- Pass 2 (fused): stream fp16 conv across ALL channels,
// norm/act/residual/exp-sum -> log -> broadcast 64-channel write. No esum scratch.
__global__ __launch_bounds__(256) void k_pass2(float* __restrict__ out) {
    __shared__ float s_rstd[G_], s_nmr[G_];

    const int bid = blockIdx.x;
    const int seg = bid % SEG2;
    const int n   = bid / SEG2;
    const int tid = threadIdx.x;
    const int wid = tid >> 5, lane = tid & 31;

    // warp g reduces group g's 32 chunk-partials
    {
        const int sg = (n*G_ + wid)*CHUNKS;
        float s  = g_part[(sg + lane)*2];
        float s2 = g_part[(sg + lane)*2 + 1];
        #pragma unroll
        for (int off = 16; off; off >>= 1) {
            s  += __shfl_down_sync(0xffffffffu, s,  off);
            s2 += __shfl_down_sync(0xffffffffu, s2, off);
        }
        if (lane == 0) {
            const float inv = 1.0f / (float)(CPG_*H_*W_);
            const float m = s * inv;
            const float v = s2 * inv - m*m;
            const float r = rsqrtf(v + EPS_);
            s_rstd[wid] = r;
            s_nmr[wid]  = -m * r;
        }
    }
    __syncthreads();

    const int px = seg*(256*PXT2) + tid*PXT2;       // 2 consecutive pixels
    const float L2E = 1.4426950408889634f;

    const __half* cvb = g_conv + (size_t)n*C_*HW_ + px;

    float es0 = 0.f, es1 = 0.f;
    #pragma unroll 8
    for (int c = 0; c < C_; ++c) {
        const unsigned u = *(const unsigned*)(cvb + (size_t)c*HW_);
        const float2 f = __half22float2(*(const __half2*)&u);
        const int g = c >> 3;
        const float rstd = s_rstd[g], nmr = s_nmr[g];

        const float v0 = fmaf(f.x, rstd, nmr);
        const float t0 = tanh_fast(v0);
        // t in (-1,1) => clip(t+3,0,6) == t+3: xr = cv + t*(t+3)/6
        const float x0 = fmaf(t0 * (1.0f/6.0f), t0 + 3.0f, f.x);
        es0 += ex2_fast(x0 * L2E);

        const float v1 = fmaf(f.y, rstd, nmr);
        const float t1 = tanh_fast(v1);
        const float x1 = fmaf(t1 * (1.0f/6.0f), t1 + 3.0f, f.y);
        es1 += ex2_fast(x1 * L2E);
    }

    float2 L;
    L.x = __logf(es0);
    L.y = __logf(es1);

    float* ob = out + (size_t)n*C_*HW_ + px;
    #pragma unroll
    for (int c = 0; c < C_; ++c)
        __stcs((float2*)(ob + (size_t)c*HW_), L);
}

extern "C" void kernel_launch(void* const* d_in, const int* in_sizes, int n_in,
                              void* d_out, int out_size) {
    const float* x   = (const float*)d_in[0];       // [8,64,256,256]
    const float* wgt = (const float*)d_in[1];       // [3,3,64]
    float* out = (float*)d_out;

    k_pass1<<<N_*G_*CHUNKS, NT>>>(x, wgt);
    k_pass2<<<N_*SEG2, 256>>>(out);
}